// round 1
// baseline (speedup 1.0000x reference)
#include <cuda_runtime.h>
#include <cuda_bf16.h>
#include <cstdint>

// Problem constants (fixed by setup_inputs)
#define B_    4
#define N_    16384
#define C_    64
#define K_    16
#define O_    64
#define RTOT  (B_ * N_)          // 65536 rows
#define TOTSAMP 1048576.0f       // B*N*K
#define BN_EPS 1e-5f

// Scratch (device globals: no allocation allowed)
__device__ float g_u[RTOT * O_];     // 16 MB : x @ (W1 - W2)^T
__device__ float g_v[RTOT * O_];     // 16 MB : x @ W2^T
__device__ float g_mx[RTOT * O_];    // 16 MB : max_k v[idx]
__device__ float g_mn[RTOT * O_];    // 16 MB : min_k v[idx]
__device__ float g_sum[O_];
__device__ float g_sq[O_];
__device__ float g_scale[O_];
__device__ float g_shift[O_];

__global__ void k_zero() {
    int t = threadIdx.x;
    if (t < O_) { g_sum[t] = 0.f; g_sq[t] = 0.f; }
}

// ---------------------------------------------------------------------------
// K1: u = x @ (W1-W2)^T, v = x @ W2^T.  Tile: 64 rows x 64 outputs per block.
// 256 threads as 16x16, each computes 4x4 micro-tile for BOTH u and v.
// ---------------------------------------------------------------------------
__global__ __launch_bounds__(256) void k_gemm(const float* __restrict__ x,
                                              const float* __restrict__ w) {
    __shared__ float sW1[64][64];    // [c][o] = W1[o][c] - W2[o][c]
    __shared__ float sW2[64][64];    // [c][o] = W2[o][c]
    __shared__ float sX[64][68];     // [row][c], padded

    int tid = threadIdx.x;

    // Load weights (transposed for conflict-free o-contiguous reads)
    for (int i = tid; i < 64 * 64; i += 256) {
        int o = i >> 6, c = i & 63;
        float w1 = w[o * 128 + c];
        float w2 = w[o * 128 + 64 + c];
        sW1[c][o] = w1 - w2;
        sW2[c][o] = w2;
    }
    // Load 64 rows of x (vectorized)
    int rowBase = blockIdx.x * 64;
    const float4* x4 = (const float4*)(x + (size_t)rowBase * 64);
    for (int i = tid; i < 64 * 16; i += 256) {
        int r = i >> 4, c4 = i & 15;
        float4 val = x4[r * 16 + c4];
        sX[r][c4 * 4 + 0] = val.x; sX[r][c4 * 4 + 1] = val.y;
        sX[r][c4 * 4 + 2] = val.z; sX[r][c4 * 4 + 3] = val.w;
    }
    __syncthreads();

    int tx = tid & 15, ty = tid >> 4;
    float au[4][4] = {}, av[4][4] = {};

#pragma unroll 8
    for (int c = 0; c < 64; ++c) {
        float a[4], b1[4], b2[4];
#pragma unroll
        for (int i = 0; i < 4; i++) a[i] = sX[ty * 4 + i][c];
#pragma unroll
        for (int j = 0; j < 4; j++) { b1[j] = sW1[c][tx * 4 + j]; b2[j] = sW2[c][tx * 4 + j]; }
#pragma unroll
        for (int i = 0; i < 4; i++)
#pragma unroll
            for (int j = 0; j < 4; j++) {
                au[i][j] = fmaf(a[i], b1[j], au[i][j]);
                av[i][j] = fmaf(a[i], b2[j], av[i][j]);
            }
    }

#pragma unroll
    for (int i = 0; i < 4; i++) {
        size_t r = (size_t)rowBase + ty * 4 + i;
        float4 uu = make_float4(au[i][0], au[i][1], au[i][2], au[i][3]);
        float4 vv = make_float4(av[i][0], av[i][1], av[i][2], av[i][3]);
        ((float4*)(g_u + r * 64))[tx] = uu;
        ((float4*)(g_v + r * 64))[tx] = vv;
    }
}

// ---------------------------------------------------------------------------
// K2: per point (b,n): gather 16 v-rows, compute max/min over k, and
// per-channel partial sums for BN stats. One warp per point (16 points/warp
// looped); lane handles channels {lane, lane+32}.
// ---------------------------------------------------------------------------
__global__ __launch_bounds__(256) void k_gather(const int* __restrict__ idx) {
    int lane = threadIdx.x & 31;
    int warpId = blockIdx.x * 8 + (threadIdx.x >> 5);
    int pbase = warpId * 16;

    float cs1_0 = 0.f, cs1_1 = 0.f, cs2_0 = 0.f, cs2_1 = 0.f;

    for (int p = 0; p < 16; ++p) {
        int point = pbase + p;
        const int* ip = idx + (size_t)point * K_;
        int b = point >> 14;                       // N = 2^14
        const float* vb = g_v + (size_t)b * N_ * O_;

        float u0 = g_u[(size_t)point * O_ + lane];
        float u1 = g_u[(size_t)point * O_ + lane + 32];

        float mx0 = -3.4e38f, mx1 = -3.4e38f, mn0 = 3.4e38f, mn1 = 3.4e38f;
        float s10 = 0.f, s11 = 0.f, s20 = 0.f, s21 = 0.f;
#pragma unroll
        for (int k = 0; k < K_; k++) {
            int j = __ldg(&ip[k]);
            const float* vr = vb + (size_t)j * O_;
            float v0 = __ldg(&vr[lane]);
            float v1 = __ldg(&vr[lane + 32]);
            mx0 = fmaxf(mx0, v0); mn0 = fminf(mn0, v0);
            s10 += v0; s20 = fmaf(v0, v0, s20);
            mx1 = fmaxf(mx1, v1); mn1 = fminf(mn1, v1);
            s11 += v1; s21 = fmaf(v1, v1, s21);
        }
        g_mx[(size_t)point * O_ + lane]      = mx0;
        g_mx[(size_t)point * O_ + lane + 32] = mx1;
        g_mn[(size_t)point * O_ + lane]      = mn0;
        g_mn[(size_t)point * O_ + lane + 32] = mn1;

        // Sum_k (u+v) = K*u + s1 ; Sum_k (u+v)^2 = K*u^2 + 2*u*s1 + s2
        cs1_0 += 16.f * u0 + s10;
        cs2_0 += fmaf(16.f * u0, u0, fmaf(2.f * u0, s10, s20));
        cs1_1 += 16.f * u1 + s11;
        cs2_1 += fmaf(16.f * u1, u1, fmaf(2.f * u1, s11, s21));
    }

    __shared__ float ssum[O_], ssq[O_];
    if (threadIdx.x < O_) { ssum[threadIdx.x] = 0.f; ssq[threadIdx.x] = 0.f; }
    __syncthreads();
    atomicAdd(&ssum[lane], cs1_0);      atomicAdd(&ssum[lane + 32], cs1_1);
    atomicAdd(&ssq[lane],  cs2_0);      atomicAdd(&ssq[lane + 32],  cs2_1);
    __syncthreads();
    if (threadIdx.x < O_) {
        atomicAdd(&g_sum[threadIdx.x], ssum[threadIdx.x]);
        atomicAdd(&g_sq[threadIdx.x],  ssq[threadIdx.x]);
    }
}

// ---------------------------------------------------------------------------
// K3: finalize BN affine per channel
// ---------------------------------------------------------------------------
__global__ void k_stats(const float* __restrict__ gamma, const float* __restrict__ beta) {
    int o = threadIdx.x;
    if (o < O_) {
        float inv = 1.0f / TOTSAMP;
        float mean = g_sum[o] * inv;
        float var  = g_sq[o] * inv - mean * mean;
        float s = rsqrtf(var + BN_EPS) * gamma[o];
        g_scale[o] = s;
        g_shift[o] = beta[o] - mean * s;
    }
}

// ---------------------------------------------------------------------------
// K4: out = relu((u + extreme_v) * scale + shift)
// scale >= 0 -> max over k commutes; scale < 0 -> use min.
// ---------------------------------------------------------------------------
__global__ __launch_bounds__(256) void k_out(float* __restrict__ out) {
    size_t i = (size_t)blockIdx.x * 256 + threadIdx.x;
    int o = (int)(i & 63);
    float s = g_scale[o], sh = g_shift[o];
    const float* m = (s >= 0.f) ? g_mx : g_mn;
    float h = fmaf(g_u[i] + m[i], s, sh);
    out[i] = fmaxf(h, 0.f);
}

extern "C" void kernel_launch(void* const* d_in, const int* in_sizes, int n_in,
                              void* d_out, int out_size) {
    const float* x     = (const float*)d_in[0];
    const int*   idx   = (const int*)  d_in[1];
    const float* w     = (const float*)d_in[2];
    const float* gamma = (const float*)d_in[3];
    const float* beta  = (const float*)d_in[4];
    float* out = (float*)d_out;

    k_zero  <<<1, 64>>>();
    k_gemm  <<<RTOT / 64, 256>>>(x, w);
    k_gather<<<RTOT / (8 * 16), 256>>>(idx);
    k_stats <<<1, 64>>>(gamma, beta);
    k_out   <<<(RTOT * O_) / 256, 256>>>(out);
}

// round 2
// speedup vs baseline: 1.1544x; 1.1544x over previous
#include <cuda_runtime.h>
#include <cuda_bf16.h>
#include <cstdint>

#define B_    4
#define N_    16384
#define C_    64
#define K_    16
#define O_    64
#define RTOT  (B_ * N_)          // 65536 rows
#define TOTSAMP 1048576.0f       // B*N*K
#define BN_EPS 1e-5f

// Scratch (device globals: allocation is forbidden)
__device__ __align__(16) float g_u[RTOT * O_];   // x @ (W1-W2)^T
__device__ __align__(16) float g_v[RTOT * O_];   // x @ W2^T
__device__ __align__(16) float g_mx[RTOT * O_];  // u + max_k v[idx]
__device__ __align__(16) float g_mn[RTOT * O_];  // u + min_k v[idx]
__device__ float g_sum[O_];
__device__ float g_sq[O_];

// ---- packed fp32x2 helpers (sm_100+ FFMA2) --------------------------------
__device__ __forceinline__ unsigned long long pack2(float a, float b) {
    unsigned long long r;
    asm("mov.b64 %0, {%1, %2};" : "=l"(r) : "f"(a), "f"(b));
    return r;
}
__device__ __forceinline__ void fma2(unsigned long long& d,
                                     unsigned long long a, unsigned long long b) {
    asm("fma.rn.f32x2 %0, %1, %2, %0;" : "+l"(d) : "l"(a), "l"(b));
}
__device__ __forceinline__ float2 unpack2(unsigned long long v) {
    float2 f;
    asm("mov.b64 {%0, %1}, %2;" : "=f"(f.x), "=f"(f.y) : "l"(v));
    return f;
}

// ---------------------------------------------------------------------------
// K1: u = x @ (W1-W2)^T, v = x @ W2^T.  64 rows x 64 outs per block,
// 16x16 threads, 4x4 micro-tile per thread for both u and v, FFMA2 inner.
// Block 0 also zeroes the stat accumulators (gather runs strictly after).
// ---------------------------------------------------------------------------
__global__ __launch_bounds__(256) void k_gemm(const float* __restrict__ x,
                                              const float* __restrict__ w) {
    __shared__ __align__(16) float sW1[64][64];   // [c][o] = W1 - W2
    __shared__ __align__(16) float sW2[64][64];   // [c][o] = W2
    __shared__ __align__(16) float sX[64][64];    // [row][c]

    int tid = threadIdx.x;
    if (blockIdx.x == 0 && tid < O_) { g_sum[tid] = 0.f; g_sq[tid] = 0.f; }

    for (int i = tid; i < 64 * 64; i += 256) {
        int o = i >> 6, c = i & 63;
        float w1 = w[o * 128 + c];
        float w2 = w[o * 128 + 64 + c];
        sW1[c][o] = w1 - w2;
        sW2[c][o] = w2;
    }
    int rowBase = blockIdx.x * 64;
    const float4* x4 = (const float4*)(x + (size_t)rowBase * 64);
    for (int i = tid; i < 64 * 16; i += 256) {
        int r = i >> 4, c4 = i & 15;
        ((float4*)&sX[r][0])[c4] = x4[r * 16 + c4];
    }
    __syncthreads();

    int tx = tid & 15, ty = tid >> 4;
    unsigned long long au[4][2] = {}, av[4][2] = {};   // 4 rows x (2 col-pairs)

    const unsigned long long* w1p;
    const unsigned long long* w2p;

#pragma unroll 4
    for (int c = 0; c < 64; ++c) {
        w1p = (const unsigned long long*)&sW1[c][0];
        w2p = (const unsigned long long*)&sW2[c][0];
        unsigned long long b1[2], b2[2];
        b1[0] = w1p[tx * 2 + 0]; b1[1] = w1p[tx * 2 + 1];
        b2[0] = w2p[tx * 2 + 0]; b2[1] = w2p[tx * 2 + 1];
#pragma unroll
        for (int i = 0; i < 4; i++) {
            float a = sX[ty * 4 + i][c];
            unsigned long long aa = pack2(a, a);
            fma2(au[i][0], aa, b1[0]);
            fma2(au[i][1], aa, b1[1]);
            fma2(av[i][0], aa, b2[0]);
            fma2(av[i][1], aa, b2[1]);
        }
    }

#pragma unroll
    for (int i = 0; i < 4; i++) {
        size_t r = (size_t)rowBase + ty * 4 + i;
        float2 u0 = unpack2(au[i][0]), u1 = unpack2(au[i][1]);
        float2 v0 = unpack2(av[i][0]), v1 = unpack2(av[i][1]);
        ((float4*)(g_u + r * 64))[tx] = make_float4(u0.x, u0.y, u1.x, u1.y);
        ((float4*)(g_v + r * 64))[tx] = make_float4(v0.x, v0.y, v1.x, v1.y);
    }
}

// ---------------------------------------------------------------------------
// K2: gather. One warp per 16 points. Half-warp per k (2 k's in flight),
// lane owns a float4 column group. shfl_xor(16) merges the two halves'
// max/min. Writes u+max and u+min so the epilogue reads a single array.
// Per-channel BN partial sums accumulated and atomically merged.
// ---------------------------------------------------------------------------
__global__ __launch_bounds__(256) void k_gather(const int* __restrict__ idx) {
    int tid  = threadIdx.x;
    int lane = tid & 31;
    int half = lane >> 4;      // 0 -> even k, 1 -> odd k
    int c4   = lane & 15;      // float4 column group
    int warpId = blockIdx.x * 8 + (tid >> 5);
    int pbase  = warpId * 16;

    float4 cs1 = {0, 0, 0, 0}, cs2 = {0, 0, 0, 0};

    for (int p = 0; p < 16; ++p) {
        int point = pbase + p;
        int b = point >> 14;                       // N = 2^14
        const float4* vb = (const float4*)(g_v + (size_t)b * N_ * O_);
        const int* ip = idx + (size_t)point * K_;

        float4 u = __ldg((const float4*)(g_u + (size_t)point * O_) + c4);

        float4 mx = make_float4(-3.4e38f, -3.4e38f, -3.4e38f, -3.4e38f);
        float4 mn = make_float4( 3.4e38f,  3.4e38f,  3.4e38f,  3.4e38f);
        float4 s1 = {0, 0, 0, 0}, s2 = {0, 0, 0, 0};
#pragma unroll
        for (int s = 0; s < 8; s++) {
            int j = __ldg(&ip[2 * s + half]);
            float4 v = __ldg(vb + (size_t)j * 16 + c4);
            mx.x = fmaxf(mx.x, v.x); mn.x = fminf(mn.x, v.x); s1.x += v.x; s2.x = fmaf(v.x, v.x, s2.x);
            mx.y = fmaxf(mx.y, v.y); mn.y = fminf(mn.y, v.y); s1.y += v.y; s2.y = fmaf(v.y, v.y, s2.y);
            mx.z = fmaxf(mx.z, v.z); mn.z = fminf(mn.z, v.z); s1.z += v.z; s2.z = fmaf(v.z, v.z, s2.z);
            mx.w = fmaxf(mx.w, v.w); mn.w = fminf(mn.w, v.w); s1.w += v.w; s2.w = fmaf(v.w, v.w, s2.w);
        }
        // merge the two k-halves (max/min need full k before writing)
        mx.x = fmaxf(mx.x, __shfl_xor_sync(0xffffffffu, mx.x, 16));
        mx.y = fmaxf(mx.y, __shfl_xor_sync(0xffffffffu, mx.y, 16));
        mx.z = fmaxf(mx.z, __shfl_xor_sync(0xffffffffu, mx.z, 16));
        mx.w = fmaxf(mx.w, __shfl_xor_sync(0xffffffffu, mx.w, 16));
        mn.x = fminf(mn.x, __shfl_xor_sync(0xffffffffu, mn.x, 16));
        mn.y = fminf(mn.y, __shfl_xor_sync(0xffffffffu, mn.y, 16));
        mn.z = fminf(mn.z, __shfl_xor_sync(0xffffffffu, mn.z, 16));
        mn.w = fminf(mn.w, __shfl_xor_sync(0xffffffffu, mn.w, 16));

        if (half == 0) {
            ((float4*)(g_mx + (size_t)point * O_))[c4] =
                make_float4(u.x + mx.x, u.y + mx.y, u.z + mx.z, u.w + mx.w);
            ((float4*)(g_mn + (size_t)point * O_))[c4] =
                make_float4(u.x + mn.x, u.y + mn.y, u.z + mn.z, u.w + mn.w);
        }

        // each lane covered 8 k's: Sum(u+v) += 8u + s1; Sum((u+v)^2) += 8u^2 + 2u*s1 + s2
        cs1.x += 8.f * u.x + s1.x;  cs2.x += fmaf(8.f * u.x, u.x, fmaf(2.f * u.x, s1.x, s2.x));
        cs1.y += 8.f * u.y + s1.y;  cs2.y += fmaf(8.f * u.y, u.y, fmaf(2.f * u.y, s1.y, s2.y));
        cs1.z += 8.f * u.z + s1.z;  cs2.z += fmaf(8.f * u.z, u.z, fmaf(2.f * u.z, s1.z, s2.z));
        cs1.w += 8.f * u.w + s1.w;  cs2.w += fmaf(8.f * u.w, u.w, fmaf(2.f * u.w, s1.w, s2.w));
    }

    __shared__ float ssum[O_], ssq[O_];
    if (tid < O_) { ssum[tid] = 0.f; ssq[tid] = 0.f; }
    __syncthreads();
    int cb = c4 * 4;
    atomicAdd(&ssum[cb + 0], cs1.x); atomicAdd(&ssq[cb + 0], cs2.x);
    atomicAdd(&ssum[cb + 1], cs1.y); atomicAdd(&ssq[cb + 1], cs2.y);
    atomicAdd(&ssum[cb + 2], cs1.z); atomicAdd(&ssq[cb + 2], cs2.z);
    atomicAdd(&ssum[cb + 3], cs1.w); atomicAdd(&ssq[cb + 3], cs2.w);
    __syncthreads();
    if (tid < O_) {
        atomicAdd(&g_sum[tid], ssum[tid]);
        atomicAdd(&g_sq[tid],  ssq[tid]);
    }
}

// ---------------------------------------------------------------------------
// K3: fused stats + epilogue. Each block recomputes the 64-channel BN affine
// (cheap, broadcast from L2), then out = relu(m * scale + shift) where m is
// u+max (scale>=0) or u+min (scale<0).
// ---------------------------------------------------------------------------
__global__ __launch_bounds__(256) void k_out(const float* __restrict__ gamma,
                                             const float* __restrict__ beta,
                                             float* __restrict__ out) {
    __shared__ __align__(16) float sc[O_];
    __shared__ __align__(16) float sh[O_];
    __shared__ int negFlag;
    int tid = threadIdx.x;
    if (tid == 0) negFlag = 0;
    __syncthreads();
    if (tid < O_) {
        float inv  = 1.0f / TOTSAMP;
        float mean = g_sum[tid] * inv;
        float var  = g_sq[tid] * inv - mean * mean;
        float s    = rsqrtf(var + BN_EPS) * gamma[tid];
        sc[tid] = s;
        sh[tid] = beta[tid] - mean * s;
        if (s < 0.f) atomicOr(&negFlag, 1);
    }
    __syncthreads();

    size_t i4 = (size_t)blockIdx.x * 256 + tid;    // float4 index
    int o4 = (int)(i4 & 15);
    float4 s4 = ((const float4*)sc)[o4];
    float4 b4 = ((const float4*)sh)[o4];

    float4 m;
    if (!negFlag) {
        m = __ldg((const float4*)g_mx + i4);
    } else {
        float4 a = __ldg((const float4*)g_mx + i4);
        float4 c = __ldg((const float4*)g_mn + i4);
        m.x = (s4.x >= 0.f) ? a.x : c.x;
        m.y = (s4.y >= 0.f) ? a.y : c.y;
        m.z = (s4.z >= 0.f) ? a.z : c.z;
        m.w = (s4.w >= 0.f) ? a.w : c.w;
    }
    float4 r;
    r.x = fmaxf(fmaf(m.x, s4.x, b4.x), 0.f);
    r.y = fmaxf(fmaf(m.y, s4.y, b4.y), 0.f);
    r.z = fmaxf(fmaf(m.z, s4.z, b4.z), 0.f);
    r.w = fmaxf(fmaf(m.w, s4.w, b4.w), 0.f);
    ((float4*)out)[i4] = r;
}

extern "C" void kernel_launch(void* const* d_in, const int* in_sizes, int n_in,
                              void* d_out, int out_size) {
    const float* x     = (const float*)d_in[0];
    const int*   idx   = (const int*)  d_in[1];
    const float* w     = (const float*)d_in[2];
    const float* gamma = (const float*)d_in[3];
    const float* beta  = (const float*)d_in[4];
    float* out = (float*)d_out;

    k_gemm  <<<RTOT / 64, 256>>>(x, w);
    k_gather<<<RTOT / (8 * 16), 256>>>(idx);
    k_out   <<<(RTOT * O_ / 4) / 256, 256>>>(gamma, beta, out);
}

// round 3
// speedup vs baseline: 1.4040x; 1.2162x over previous
#include <cuda_runtime.h>
#include <cuda_bf16.h>
#include <cstdint>

#define B_    4
#define N_    16384
#define C_    64
#define K_    16
#define O_    64
#define RTOT  (B_ * N_)          // 65536 rows
#define TOTSAMP 1048576.0f       // B*N*K
#define BN_EPS 1e-5f

// Scratch (device globals: allocation is forbidden)
__device__ __align__(16) float g_u[RTOT * O_];   // x @ (W1-W2)^T
__device__ __align__(16) float g_v[RTOT * O_];   // x @ W2^T
__device__ __align__(16) float g_mx[RTOT * O_];  // u + max_k v[idx]
__device__ __align__(16) float g_mn[RTOT * O_];  // u + min_k v[idx]
__device__ float g_sum[O_];
__device__ float g_sq[O_];

// ---- packed fp32x2 helpers (sm_100+ FFMA2) --------------------------------
__device__ __forceinline__ unsigned long long pack2(float a, float b) {
    unsigned long long r;
    asm("mov.b64 %0, {%1, %2};" : "=l"(r) : "f"(a), "f"(b));
    return r;
}
__device__ __forceinline__ void fma2(unsigned long long& d,
                                     unsigned long long a, unsigned long long b) {
    asm("fma.rn.f32x2 %0, %1, %2, %0;" : "+l"(d) : "l"(a), "l"(b));
}
__device__ __forceinline__ float2 unpack2(unsigned long long v) {
    float2 f;
    asm("mov.b64 {%0, %1}, %2;" : "=f"(f.x), "=f"(f.y) : "l"(v));
    return f;
}

// ---------------------------------------------------------------------------
// K1: u = x @ (W1-W2)^T, v = x @ W2^T.
// 128 rows x (64 u-cols + 64 v-cols) per block. 16x16 threads; each thread
// owns an 8-row x (4 u + 4 v)-col micro-tile -> 32 FFMA2 per c-iteration
// against ~4 LDS.128 + 8 broadcast LDS.32. Doubles FMA-per-smem-byte vs R2.
// ---------------------------------------------------------------------------
__global__ __launch_bounds__(256) void k_gemm(const float* __restrict__ x,
                                              const float* __restrict__ w) {
    __shared__ __align__(16) float sW1[64][64];   // [c][o] = W1 - W2
    __shared__ __align__(16) float sW2[64][64];   // [c][o] = W2
    __shared__ __align__(16) float sX[128][64];   // [row][c]

    int tid = threadIdx.x;
    if (blockIdx.x == 0 && tid < O_) { g_sum[tid] = 0.f; g_sq[tid] = 0.f; }

    // Weights: task (o, c4) loads W1[o][c4*4..+3] and W2[o][c4*4..+3],
    // writes transposed diff/val. 64*16 = 1024 tasks.
    const float4* w4 = (const float4*)w;   // row o = 32 float4 (16 W1 + 16 W2)
    for (int i = tid; i < 1024; i += 256) {
        int o  = i & 63;
        int c4 = i >> 6;
        float4 w1 = w4[o * 32 + c4];
        float4 w2 = w4[o * 32 + 16 + c4];
        int c = c4 * 4;
        sW1[c + 0][o] = w1.x - w2.x;  sW2[c + 0][o] = w2.x;
        sW1[c + 1][o] = w1.y - w2.y;  sW2[c + 1][o] = w2.y;
        sW1[c + 2][o] = w1.z - w2.z;  sW2[c + 2][o] = w2.z;
        sW1[c + 3][o] = w1.w - w2.w;  sW2[c + 3][o] = w2.w;
    }
    int rowBase = blockIdx.x * 128;
    const float4* x4 = (const float4*)(x + (size_t)rowBase * 64);
    for (int i = tid; i < 128 * 16; i += 256) {
        int r = i >> 4, c4 = i & 15;
        ((float4*)&sX[r][0])[c4] = x4[i];
    }
    __syncthreads();

    int tx = tid & 15, ty = tid >> 4;
    unsigned long long au[8][2] = {}, av[8][2] = {};

#pragma unroll 4
    for (int c = 0; c < 64; ++c) {
        const unsigned long long* w1p = (const unsigned long long*)&sW1[c][0];
        const unsigned long long* w2p = (const unsigned long long*)&sW2[c][0];
        unsigned long long b1[2], b2[2];
        b1[0] = w1p[tx * 2 + 0]; b1[1] = w1p[tx * 2 + 1];
        b2[0] = w2p[tx * 2 + 0]; b2[1] = w2p[tx * 2 + 1];
#pragma unroll
        for (int i = 0; i < 8; i++) {
            float a = sX[ty * 8 + i][c];
            unsigned long long aa = pack2(a, a);
            fma2(au[i][0], aa, b1[0]);
            fma2(au[i][1], aa, b1[1]);
            fma2(av[i][0], aa, b2[0]);
            fma2(av[i][1], aa, b2[1]);
        }
    }

#pragma unroll
    for (int i = 0; i < 8; i++) {
        size_t r = (size_t)rowBase + ty * 8 + i;
        float2 u0 = unpack2(au[i][0]), u1 = unpack2(au[i][1]);
        float2 v0 = unpack2(av[i][0]), v1 = unpack2(av[i][1]);
        ((float4*)(g_u + r * 64))[tx] = make_float4(u0.x, u0.y, u1.x, u1.y);
        ((float4*)(g_v + r * 64))[tx] = make_float4(v0.x, v0.y, v1.x, v1.y);
    }
}

// ---------------------------------------------------------------------------
// K2: gather. One warp per 16 points. Half-warp per k (2 k's in flight),
// lane owns a float4 column group; shfl_xor(16) merges halves' max/min.
// Writes u+max / u+min; accumulates per-channel BN partial sums.
// ---------------------------------------------------------------------------
__global__ __launch_bounds__(256) void k_gather(const int* __restrict__ idx) {
    int tid  = threadIdx.x;
    int lane = tid & 31;
    int half = lane >> 4;
    int c4   = lane & 15;
    int warpId = blockIdx.x * 8 + (tid >> 5);
    int pbase  = warpId * 16;

    float4 cs1 = {0, 0, 0, 0}, cs2 = {0, 0, 0, 0};

    for (int p = 0; p < 16; ++p) {
        int point = pbase + p;
        int b = point >> 14;
        const float4* vb = (const float4*)(g_v + (size_t)b * N_ * O_);
        const int* ip = idx + (size_t)point * K_;

        float4 u = __ldg((const float4*)(g_u + (size_t)point * O_) + c4);

        float4 mx = make_float4(-3.4e38f, -3.4e38f, -3.4e38f, -3.4e38f);
        float4 mn = make_float4( 3.4e38f,  3.4e38f,  3.4e38f,  3.4e38f);
        float4 s1 = {0, 0, 0, 0}, s2 = {0, 0, 0, 0};
#pragma unroll
        for (int s = 0; s < 8; s++) {
            int j = __ldg(&ip[2 * s + half]);
            float4 v = __ldg(vb + (size_t)j * 16 + c4);
            mx.x = fmaxf(mx.x, v.x); mn.x = fminf(mn.x, v.x); s1.x += v.x; s2.x = fmaf(v.x, v.x, s2.x);
            mx.y = fmaxf(mx.y, v.y); mn.y = fminf(mn.y, v.y); s1.y += v.y; s2.y = fmaf(v.y, v.y, s2.y);
            mx.z = fmaxf(mx.z, v.z); mn.z = fminf(mn.z, v.z); s1.z += v.z; s2.z = fmaf(v.z, v.z, s2.z);
            mx.w = fmaxf(mx.w, v.w); mn.w = fminf(mn.w, v.w); s1.w += v.w; s2.w = fmaf(v.w, v.w, s2.w);
        }
        mx.x = fmaxf(mx.x, __shfl_xor_sync(0xffffffffu, mx.x, 16));
        mx.y = fmaxf(mx.y, __shfl_xor_sync(0xffffffffu, mx.y, 16));
        mx.z = fmaxf(mx.z, __shfl_xor_sync(0xffffffffu, mx.z, 16));
        mx.w = fmaxf(mx.w, __shfl_xor_sync(0xffffffffu, mx.w, 16));
        mn.x = fminf(mn.x, __shfl_xor_sync(0xffffffffu, mn.x, 16));
        mn.y = fminf(mn.y, __shfl_xor_sync(0xffffffffu, mn.y, 16));
        mn.z = fminf(mn.z, __shfl_xor_sync(0xffffffffu, mn.z, 16));
        mn.w = fminf(mn.w, __shfl_xor_sync(0xffffffffu, mn.w, 16));

        if (half == 0) {
            ((float4*)(g_mx + (size_t)point * O_))[c4] =
                make_float4(u.x + mx.x, u.y + mx.y, u.z + mx.z, u.w + mx.w);
            ((float4*)(g_mn + (size_t)point * O_))[c4] =
                make_float4(u.x + mn.x, u.y + mn.y, u.z + mn.z, u.w + mn.w);
        }

        cs1.x += 8.f * u.x + s1.x;  cs2.x += fmaf(8.f * u.x, u.x, fmaf(2.f * u.x, s1.x, s2.x));
        cs1.y += 8.f * u.y + s1.y;  cs2.y += fmaf(8.f * u.y, u.y, fmaf(2.f * u.y, s1.y, s2.y));
        cs1.z += 8.f * u.z + s1.z;  cs2.z += fmaf(8.f * u.z, u.z, fmaf(2.f * u.z, s1.z, s2.z));
        cs1.w += 8.f * u.w + s1.w;  cs2.w += fmaf(8.f * u.w, u.w, fmaf(2.f * u.w, s1.w, s2.w));
    }

    __shared__ float ssum[O_], ssq[O_];
    if (tid < O_) { ssum[tid] = 0.f; ssq[tid] = 0.f; }
    __syncthreads();
    int cb = c4 * 4;
    atomicAdd(&ssum[cb + 0], cs1.x); atomicAdd(&ssq[cb + 0], cs2.x);
    atomicAdd(&ssum[cb + 1], cs1.y); atomicAdd(&ssq[cb + 1], cs2.y);
    atomicAdd(&ssum[cb + 2], cs1.z); atomicAdd(&ssq[cb + 2], cs2.z);
    atomicAdd(&ssum[cb + 3], cs1.w); atomicAdd(&ssq[cb + 3], cs2.w);
    __syncthreads();
    if (tid < O_) {
        atomicAdd(&g_sum[tid], ssum[tid]);
        atomicAdd(&g_sq[tid],  ssq[tid]);
    }
}

// ---------------------------------------------------------------------------
// K3: fused stats + epilogue.
// ---------------------------------------------------------------------------
__global__ __launch_bounds__(256) void k_out(const float* __restrict__ gamma,
                                             const float* __restrict__ beta,
                                             float* __restrict__ out) {
    __shared__ __align__(16) float sc[O_];
    __shared__ __align__(16) float sh[O_];
    __shared__ int negFlag;
    int tid = threadIdx.x;
    if (tid == 0) negFlag = 0;
    __syncthreads();
    if (tid < O_) {
        float inv  = 1.0f / TOTSAMP;
        float mean = g_sum[tid] * inv;
        float var  = g_sq[tid] * inv - mean * mean;
        float s    = rsqrtf(var + BN_EPS) * gamma[tid];
        sc[tid] = s;
        sh[tid] = beta[tid] - mean * s;
        if (s < 0.f) atomicOr(&negFlag, 1);
    }
    __syncthreads();

    size_t i4 = (size_t)blockIdx.x * 256 + tid;
    int o4 = (int)(i4 & 15);
    float4 s4 = ((const float4*)sc)[o4];
    float4 b4 = ((const float4*)sh)[o4];

    float4 m;
    if (!negFlag) {
        m = __ldg((const float4*)g_mx + i4);
    } else {
        float4 a = __ldg((const float4*)g_mx + i4);
        float4 c = __ldg((const float4*)g_mn + i4);
        m.x = (s4.x >= 0.f) ? a.x : c.x;
        m.y = (s4.y >= 0.f) ? a.y : c.y;
        m.z = (s4.z >= 0.f) ? a.z : c.z;
        m.w = (s4.w >= 0.f) ? a.w : c.w;
    }
    float4 r;
    r.x = fmaxf(fmaf(m.x, s4.x, b4.x), 0.f);
    r.y = fmaxf(fmaf(m.y, s4.y, b4.y), 0.f);
    r.z = fmaxf(fmaf(m.z, s4.z, b4.z), 0.f);
    r.w = fmaxf(fmaf(m.w, s4.w, b4.w), 0.f);
    ((float4*)out)[i4] = r;
}

extern "C" void kernel_launch(void* const* d_in, const int* in_sizes, int n_in,
                              void* d_out, int out_size) {
    const float* x     = (const float*)d_in[0];
    const int*   idx   = (const int*)  d_in[1];
    const float* w     = (const float*)d_in[2];
    const float* gamma = (const float*)d_in[3];
    const float* beta  = (const float*)d_in[4];
    float* out = (float*)d_out;

    k_gemm  <<<RTOT / 128, 256>>>(x, w);
    k_gather<<<RTOT / (8 * 16), 256>>>(idx);
    k_out   <<<(RTOT * O_ / 4) / 256, 256>>>(gamma, beta, out);
}